// round 2
// baseline (speedup 1.0000x reference)
#include <cuda_runtime.h>

#define N_NODES 100000
#define HID 128
#define NCLS 20
#define NEDGE 625000

#define TM 64          // nodes per block in fused kernel
#define AS_LD 68       // padded lead dim for transposed A tile (bank-conflict free, 16B aligned)
#define HS_LD 132      // padded lead dim for H tile

// Scratch (device globals: allocation-free per harness rules)
__device__ float g_sum[(size_t)N_NODES * HID];
__device__ float g_cnt[N_NODES];
__device__ int   g_is64;

// ---------------------------------------------------------------------------
// Detect edge_index dtype: int64 vs int32 (JAX x64-disabled gives int32 even
// though the reference asks for int64). Interpreting int32 data as int64
// yields values >= 2^32 except when the adjacent word is 0 (~1e-5 prob), so
// sampling 256 entries separates the cases with overwhelming margin.
// ---------------------------------------------------------------------------
__global__ void k_detect(const void* __restrict__ ei_raw) {
    if (blockIdx.x != 0 || threadIdx.x != 0) return;
    const long long* e64 = (const long long*)ei_raw;
    int ok = 0;
#pragma unroll 4
    for (int i = 0; i < 256; i++) {
        long long v = e64[i];
        if (v >= 0 && v < N_NODES) ok++;
    }
    g_is64 = (ok >= 250) ? 1 : 0;
}

// ---------------------------------------------------------------------------
// Zero the scatter accumulators
// ---------------------------------------------------------------------------
__global__ void k_zero() {
    int tid = blockIdx.x * blockDim.x + threadIdx.x;
    int stride = gridDim.x * blockDim.x;
    float4 z = make_float4(0.f, 0.f, 0.f, 0.f);
    float4* s4 = reinterpret_cast<float4*>(g_sum);
    const int n4 = N_NODES * HID / 4;
    for (int i = tid; i < n4; i += stride) s4[i] = z;
    for (int i = tid; i < N_NODES; i += stride) g_cnt[i] = 0.f;
}

// ---------------------------------------------------------------------------
// Edge scatter: warp per edge. Lane l handles float4 chunk l of the 128-dim
// feature. Vector reduction (red.global.add.v4.f32) = 1 REDG per lane.
// ---------------------------------------------------------------------------
__global__ void k_scatter(const float* __restrict__ x,
                          const void* __restrict__ ei_raw) {
    int gtid = blockIdx.x * blockDim.x + threadIdx.x;
    int e = gtid >> 5;
    int lane = threadIdx.x & 31;
    if (e >= NEDGE) return;

    long long s = 0, d = 0;
    if (lane == 0) {
        if (g_is64) {
            const long long* e64 = (const long long*)ei_raw;
            s = e64[e];
            d = e64[NEDGE + e];
        } else {
            const int* e32 = (const int*)ei_raw;
            s = e32[e];
            d = e32[NEDGE + e];
        }
    }
    s = __shfl_sync(0xffffffffu, s, 0);
    d = __shfl_sync(0xffffffffu, d, 0);
    // Safety guard: never fault even if dtype detection were wrong.
    if (s < 0 || s >= N_NODES || d < 0 || d >= N_NODES) return;

    float4 v = *reinterpret_cast<const float4*>(&x[(size_t)s * HID + lane * 4]);
    float* p = &g_sum[(size_t)d * HID + lane * 4];
    asm volatile("red.global.add.v4.f32 [%0], {%1, %2, %3, %4};"
                 :: "l"(p), "f"(v.x), "f"(v.y), "f"(v.z), "f"(v.w)
                 : "memory");
    if (lane == 0) atomicAdd(&g_cnt[d], 1.0f);
}

// ---------------------------------------------------------------------------
// Fused: aggr = sum/max(cnt,1); h = [aggr|x] @ [W_l;W_r] + b_l;
//        out = rownorm(h) @ colnorm(W_cls)
// Block: 256 threads, 64 nodes x 128 out cols, K=256.
// Thread micro-tile: 4 nodes x 8 cols.
// ---------------------------------------------------------------------------
__global__ void __launch_bounds__(256, 1)
k_fused(const float* __restrict__ x,
        const float* __restrict__ W_l,
        const float* __restrict__ b_l,
        const float* __restrict__ W_r,
        const float* __restrict__ W_cls,
        float* __restrict__ out) {
    extern __shared__ float sm[];
    float* Ws   = sm;                    // [256][128]  = 32768 floats
    float* As   = Ws + 256 * 128;        // [256][AS_LD]= 17408 floats (reused as Hs)
    float* Wn   = As + 256 * AS_LD;      // [128][20]   = 2560 floats
    float* bs   = Wn + HID * NCLS;       // 128
    float* rinv = bs + HID;              // 64
    float* ninv = rinv + TM;             // 32 (20 used)

    const int tid  = threadIdx.x;
    const int row0 = blockIdx.x * TM;

    // ---- cooperative loads ----
    {   // concat weights: rows 0..127 = W_l, 128..255 = W_r
        float4* Ws4 = reinterpret_cast<float4*>(Ws);
        const float4* Wl4 = reinterpret_cast<const float4*>(W_l);
        const float4* Wr4 = reinterpret_cast<const float4*>(W_r);
        for (int i = tid; i < 256 * 32; i += 256)
            Ws4[i] = (i < 128 * 32) ? Wl4[i] : Wr4[i - 128 * 32];
    }
    if (tid < HID) bs[tid] = b_l[tid];
    for (int i = tid; i < HID * NCLS; i += 256) Wn[i] = W_cls[i];

    // A tile, transposed: As[k][m]; k<128 = scaled aggregate, k>=128 = x
    for (int idx = tid; idx < TM * 32; idx += 256) {
        int m = idx >> 5, c = idx & 31;
        int r = row0 + m;
        float4 sv = make_float4(0.f, 0.f, 0.f, 0.f);
        float4 xv = make_float4(0.f, 0.f, 0.f, 0.f);
        if (r < N_NODES) {
            float inv = 1.0f / fmaxf(g_cnt[r], 1.0f);
            float4 t = *reinterpret_cast<const float4*>(&g_sum[(size_t)r * HID + c * 4]);
            sv.x = t.x * inv; sv.y = t.y * inv; sv.z = t.z * inv; sv.w = t.w * inv;
            xv = *reinterpret_cast<const float4*>(&x[(size_t)r * HID + c * 4]);
        }
        int k0 = c * 4;
        As[(k0 + 0) * AS_LD + m] = sv.x;
        As[(k0 + 1) * AS_LD + m] = sv.y;
        As[(k0 + 2) * AS_LD + m] = sv.z;
        As[(k0 + 3) * AS_LD + m] = sv.w;
        As[(128 + k0 + 0) * AS_LD + m] = xv.x;
        As[(128 + k0 + 1) * AS_LD + m] = xv.y;
        As[(128 + k0 + 2) * AS_LD + m] = xv.z;
        As[(128 + k0 + 3) * AS_LD + m] = xv.w;
    }
    __syncthreads();

    // ---- column-normalize W_cls ----
    if (tid < NCLS) {
        float ss = 0.f;
        for (int j = 0; j < HID; j++) { float v = Wn[j * NCLS + tid]; ss += v * v; }
        ninv[tid] = 1.0f / fmaxf(sqrtf(ss), 1e-12f);
    }
    __syncthreads();
    for (int i = tid; i < HID * NCLS; i += 256) Wn[i] *= ninv[i % NCLS];
    // (ordered before epilogue reads by the post-K __syncthreads)

    // ---- main GEMM: acc[4][8] over K=256 ----
    const int tcol = tid & 15;   // 16 groups -> 8 cols each
    const int trow = tid >> 4;   // 16 groups -> 4 rows each
    float acc[4][8];
#pragma unroll
    for (int i = 0; i < 4; i++)
#pragma unroll
        for (int j = 0; j < 8; j++) acc[i][j] = 0.f;

#pragma unroll 4
    for (int k = 0; k < 256; k++) {
        float4 a  = *reinterpret_cast<float4*>(&As[k * AS_LD + trow * 4]);
        float4 b0 = *reinterpret_cast<float4*>(&Ws[k * 128 + tcol * 8]);
        float4 b1 = *reinterpret_cast<float4*>(&Ws[k * 128 + tcol * 8 + 4]);
        float av[4] = {a.x, a.y, a.z, a.w};
        float bv[8] = {b0.x, b0.y, b0.z, b0.w, b1.x, b1.y, b1.z, b1.w};
#pragma unroll
        for (int i = 0; i < 4; i++)
#pragma unroll
            for (int j = 0; j < 8; j++)
                acc[i][j] += av[i] * bv[j];
    }

    // bias
    float bb[8];
#pragma unroll
    for (int j = 0; j < 8; j++) bb[j] = bs[tcol * 8 + j];
#pragma unroll
    for (int i = 0; i < 4; i++)
#pragma unroll
        for (int j = 0; j < 8; j++) acc[i][j] += bb[j];

    __syncthreads();   // everyone done reading As; also orders Wn scaling

    // ---- write H into reused As smem ----
    float* Hs = As;    // [64][HS_LD]
#pragma unroll
    for (int i = 0; i < 4; i++) {
        float4 h0 = make_float4(acc[i][0], acc[i][1], acc[i][2], acc[i][3]);
        float4 h1 = make_float4(acc[i][4], acc[i][5], acc[i][6], acc[i][7]);
        *reinterpret_cast<float4*>(&Hs[(trow * 4 + i) * HS_LD + tcol * 8])     = h0;
        *reinterpret_cast<float4*>(&Hs[(trow * 4 + i) * HS_LD + tcol * 8 + 4]) = h1;
    }
    __syncthreads();

    // ---- per-row inverse norms ----
    {
        int w = tid >> 5, lane = tid & 31;
        for (int r = w; r < TM; r += 8) {
            float4 v = *reinterpret_cast<float4*>(&Hs[r * HS_LD + lane * 4]);
            float ss = v.x * v.x + v.y * v.y + v.z * v.z + v.w * v.w;
#pragma unroll
            for (int o = 16; o > 0; o >>= 1) ss += __shfl_xor_sync(0xffffffffu, ss, o);
            if (lane == 0) rinv[r] = 1.0f / fmaxf(sqrtf(ss), 1e-12f);
        }
    }
    __syncthreads();

    // ---- classifier: out[r][c] = (H[r]/||H[r]||) . Wn[:,c] ----
    for (int idx = tid; idx < TM * NCLS; idx += 256) {
        int r = idx / NCLS, c = idx % NCLS;
        int gr = row0 + r;
        if (gr >= N_NODES) continue;
        float s = 0.f;
#pragma unroll 8
        for (int j = 0; j < HID; j++)
            s += Hs[r * HS_LD + j] * Wn[j * NCLS + c];
        out[(size_t)gr * NCLS + c] = s * rinv[r];
    }
}

// ---------------------------------------------------------------------------
extern "C" void kernel_launch(void* const* d_in, const int* in_sizes, int n_in,
                              void* d_out, int out_size) {
    const float* x     = (const float*)d_in[0];
    const void*  ei    = d_in[1];
    const float* W_l   = (const float*)d_in[2];
    const float* b_l   = (const float*)d_in[3];
    const float* W_r   = (const float*)d_in[4];
    const float* W_cls = (const float*)d_in[5];
    float*       out   = (float*)d_out;

    const int smem_bytes = (256 * 128 + 256 * AS_LD + HID * NCLS + HID + TM + 32) * 4;
    cudaFuncSetAttribute(k_fused, cudaFuncAttributeMaxDynamicSharedMemorySize, smem_bytes);

    k_detect<<<1, 32>>>(ei);
    k_zero<<<2048, 256>>>();

    long long scatter_threads = (long long)NEDGE * 32;
    k_scatter<<<(int)((scatter_threads + 255) / 256), 256>>>(x, ei);

    int blocks = (N_NODES + TM - 1) / TM;
    k_fused<<<blocks, 256, smem_bytes>>>(x, W_l, b_l, W_r, W_cls, out);
}

// round 3
// speedup vs baseline: 1.4274x; 1.4274x over previous
#include <cuda_runtime.h>

#define N_NODES 100000
#define HID 128
#define NCLS 20
#define NEDGE 625000

#define TM 128         // nodes per block
#define KC 64          // K chunk
#define AS_LD 132      // padded lead dim for transposed A chunk

// Scratch (device globals: allocation-free per harness rules)
__device__ float g_sum[(size_t)N_NODES * HID];
__device__ float g_cnt[N_NODES];
__device__ int   g_is64;

// ---------------------------------------------------------------------------
// Detect edge_index dtype: int64 vs int32 (JAX x64-disabled gives int32).
// One warp, 8 samples/lane: int32 data viewed as int64 is in [0,N) only when
// the adjacent word happens to be 0 (~1e-5), so 250/256 separates cleanly.
// ---------------------------------------------------------------------------
__global__ void k_detect(const void* __restrict__ ei_raw) {
    const long long* e64 = (const long long*)ei_raw;
    int lane = threadIdx.x & 31;
    int ok = 0;
#pragma unroll
    for (int i = 0; i < 8; i++) {
        long long v = e64[lane * 8 + i];
        ok += (v >= 0 && v < N_NODES) ? 1 : 0;
    }
#pragma unroll
    for (int o = 16; o; o >>= 1) ok += __shfl_xor_sync(0xffffffffu, ok, o);
    if (lane == 0) g_is64 = (ok >= 250) ? 1 : 0;
}

// ---------------------------------------------------------------------------
// Zero the scatter accumulators
// ---------------------------------------------------------------------------
__global__ void k_zero() {
    int tid = blockIdx.x * blockDim.x + threadIdx.x;
    int stride = gridDim.x * blockDim.x;
    float4 z = make_float4(0.f, 0.f, 0.f, 0.f);
    float4* s4 = reinterpret_cast<float4*>(g_sum);
    const int n4 = N_NODES * HID / 4;
    for (int i = tid; i < n4; i += stride) s4[i] = z;
    for (int i = tid; i < N_NODES; i += stride) g_cnt[i] = 0.f;
}

// ---------------------------------------------------------------------------
// Edge scatter: warp per edge, lane l owns float4 chunk l. red.global.add.v4.
// ---------------------------------------------------------------------------
__global__ void k_scatter(const float* __restrict__ x,
                          const void* __restrict__ ei_raw) {
    int gtid = blockIdx.x * blockDim.x + threadIdx.x;
    int e = gtid >> 5;
    int lane = threadIdx.x & 31;
    if (e >= NEDGE) return;

    long long s = 0, d = 0;
    if (lane == 0) {
        if (g_is64) {
            const long long* e64 = (const long long*)ei_raw;
            s = e64[e];
            d = e64[NEDGE + e];
        } else {
            const int* e32 = (const int*)ei_raw;
            s = e32[e];
            d = e32[NEDGE + e];
        }
    }
    s = __shfl_sync(0xffffffffu, s, 0);
    d = __shfl_sync(0xffffffffu, d, 0);
    if (s < 0 || s >= N_NODES || d < 0 || d >= N_NODES) return;

    float4 v = *reinterpret_cast<const float4*>(&x[(size_t)s * HID + lane * 4]);
    float* p = &g_sum[(size_t)d * HID + lane * 4];
    asm volatile("red.global.add.v4.f32 [%0], {%1, %2, %3, %4};"
                 :: "l"(p), "f"(v.x), "f"(v.y), "f"(v.z), "f"(v.w)
                 : "memory");
    if (lane == 0) atomicAdd(&g_cnt[d], 1.0f);
}

// ---------------------------------------------------------------------------
// Fused: aggr = sum/max(cnt,1); h = [aggr|x] @ [W_l;W_r] + b_l;
//        out = rownorm(h) @ colnorm(W_cls)
// Block: 256 threads -> 128 nodes x 128 cols, K=256 in 4 chunks of 64.
// Thread micro-tile 8x8 (1 B smem / FMA). Epilogue fully register-resident.
// Thread map: trow = tid>>4 (0..15), tcol = tid&15; the 16 threads sharing a
// row group are consecutive lanes -> 16-lane shuffle reductions.
// ---------------------------------------------------------------------------
__global__ void __launch_bounds__(256, 1)
k_fused(const float* __restrict__ x,
        const float* __restrict__ W_l,
        const float* __restrict__ b_l,
        const float* __restrict__ W_r,
        const float* __restrict__ W_cls,
        float* __restrict__ out) {
    extern __shared__ float sm[];
    float* Bs = sm;                       // [256][128] concat weights = 131072 B
    float* As = Bs + 256 * HID;           // [2][KC][AS_LD]             =  67584 B
    float* Wn = As + 2 * KC * AS_LD;      // [128][20]                  =  10240 B
    float* bs = Wn + HID * NCLS;          // 128
    float* rc = bs + HID;                 // 128 (1/max(cnt,1) per row)
    float* nv = rc + TM;                  // 32  (col inv-norms of W_cls)

    const int tid  = threadIdx.x;
    const int row0 = blockIdx.x * TM;
    const int trow = tid >> 4;            // 0..15 -> rows trow*8..+7
    const int tcol = tid & 15;            // 0..15 -> cols tcol*8..+7

    // ---- phase A: weights / bias / counts into smem ----
    {
        float4* Bs4 = reinterpret_cast<float4*>(Bs);
        const float4* Wl4 = reinterpret_cast<const float4*>(W_l);
        const float4* Wr4 = reinterpret_cast<const float4*>(W_r);
#pragma unroll
        for (int i = 0; i < 32; i++) {
            int idx = tid + i * 256;
            Bs4[idx] = (idx < 128 * 32) ? Wl4[idx] : Wr4[idx - 128 * 32];
        }
    }
    for (int i = tid; i < HID * NCLS; i += 256) Wn[i] = W_cls[i];
    if (tid < 128) {
        bs[tid] = b_l[tid];
        int r = row0 + tid;
        rc[tid] = (r < N_NODES) ? 1.0f / fmaxf(g_cnt[r], 1.0f) : 0.0f;
    }
    __syncthreads();

    // ---- phase B: prefetch chunk 0 while computing W_cls column norms ----
    float4 pf[8];
#pragma unroll
    for (int i = 0; i < 8; i++) {
        int t = tid + i * 256;
        int m = t & 127, q = t >> 7;           // m: row in tile, q: k-quad
        int r = row0 + m;
        pf[i] = make_float4(0.f, 0.f, 0.f, 0.f);
        if (r < N_NODES)
            pf[i] = *reinterpret_cast<const float4*>(&g_sum[(size_t)r * HID + q * 4]);
    }
    if (tid < NCLS) {
        float ss = 0.f;
        for (int j = 0; j < HID; j++) { float v = Wn[j * NCLS + tid]; ss += v * v; }
        nv[tid] = 1.0f / fmaxf(sqrtf(ss), 1e-12f);
    }
#pragma unroll
    for (int i = 0; i < 8; i++) {
        int t = tid + i * 256;
        int m = t & 127, q = t >> 7;
        float sc = rc[m];
        As[(q * 4 + 0) * AS_LD + m] = pf[i].x * sc;
        As[(q * 4 + 1) * AS_LD + m] = pf[i].y * sc;
        As[(q * 4 + 2) * AS_LD + m] = pf[i].z * sc;
        As[(q * 4 + 3) * AS_LD + m] = pf[i].w * sc;
    }
    __syncthreads();
    // scale W_cls columns (read in classifier; ordered by the chunk-loop syncs)
    for (int i = tid; i < HID * NCLS; i += 256) Wn[i] *= nv[i % NCLS];

    // ---- main GEMM: 4 chunks of K=64, acc[8][8] ----
    float acc[8][8];
#pragma unroll
    for (int i = 0; i < 8; i++)
#pragma unroll
        for (int j = 0; j < 8; j++) acc[i][j] = 0.f;

    for (int c = 0; c < 4; c++) {
        // prefetch next chunk into registers (latency hidden behind compute)
        if (c < 3) {
            int cn = c + 1;
#pragma unroll
            for (int i = 0; i < 8; i++) {
                int t = tid + i * 256;
                int m = t & 127, q = t >> 7;
                int r = row0 + m;
                int gk = cn * KC + q * 4;
                pf[i] = make_float4(0.f, 0.f, 0.f, 0.f);
                if (r < N_NODES) {
                    const float* src = (cn < 2)
                        ? &g_sum[(size_t)r * HID + gk]
                        : &x[(size_t)r * HID + (gk - HID)];
                    pf[i] = *reinterpret_cast<const float4*>(src);
                }
            }
        }
        // compute chunk c
        const float* Ac = &As[(c & 1) * KC * AS_LD];
        const float* Bc = &Bs[(c * KC) * HID];
#pragma unroll 4
        for (int k = 0; k < KC; k++) {
            float4 a0 = *reinterpret_cast<const float4*>(&Ac[k * AS_LD + trow * 8]);
            float4 a1 = *reinterpret_cast<const float4*>(&Ac[k * AS_LD + trow * 8 + 4]);
            float4 b0 = *reinterpret_cast<const float4*>(&Bc[k * HID + tcol * 8]);
            float4 b1 = *reinterpret_cast<const float4*>(&Bc[k * HID + tcol * 8 + 4]);
            float av[8] = {a0.x, a0.y, a0.z, a0.w, a1.x, a1.y, a1.z, a1.w};
            float bv[8] = {b0.x, b0.y, b0.z, b0.w, b1.x, b1.y, b1.z, b1.w};
#pragma unroll
            for (int i = 0; i < 8; i++)
#pragma unroll
                for (int j = 0; j < 8; j++)
                    acc[i][j] += av[i] * bv[j];
        }
        // stage next chunk (writes the buffer NOT read by chunk c) and sync
        if (c < 3) {
            float* dst = &As[((c + 1) & 1) * KC * AS_LD];
            bool scale = (c + 1) < 2;
#pragma unroll
            for (int i = 0; i < 8; i++) {
                int t = tid + i * 256;
                int m = t & 127, q = t >> 7;
                float sc = scale ? rc[m] : 1.0f;
                dst[(q * 4 + 0) * AS_LD + m] = pf[i].x * sc;
                dst[(q * 4 + 1) * AS_LD + m] = pf[i].y * sc;
                dst[(q * 4 + 2) * AS_LD + m] = pf[i].z * sc;
                dst[(q * 4 + 3) * AS_LD + m] = pf[i].w * sc;
            }
            __syncthreads();
        }
    }

    // ---- epilogue: bias + row L2 norm (16-lane butterfly), all in registers ----
    float bb[8];
#pragma unroll
    for (int j = 0; j < 8; j++) bb[j] = bs[tcol * 8 + j];
#pragma unroll
    for (int i = 0; i < 8; i++) {
        float ss = 0.f;
#pragma unroll
        for (int j = 0; j < 8; j++) {
            acc[i][j] += bb[j];
            ss += acc[i][j] * acc[i][j];
        }
#pragma unroll
        for (int o = 1; o < 16; o <<= 1)
            ss += __shfl_xor_sync(0xffffffffu, ss, o);
        float rs = 1.0f / fmaxf(sqrtf(ss), 1e-12f);
#pragma unroll
        for (int j = 0; j < 8; j++) acc[i][j] *= rs;
    }

    // ---- classifier: 4 classes per pass, 16-lane shuffle reduction ----
#pragma unroll
    for (int c0 = 0; c0 < NCLS; c0 += 4) {
        float w[8][4];
#pragma unroll
        for (int j = 0; j < 8; j++)
#pragma unroll
            for (int cc = 0; cc < 4; cc++)
                w[j][cc] = Wn[(tcol * 8 + j) * NCLS + c0 + cc];
        float p[8][4];
#pragma unroll
        for (int i = 0; i < 8; i++)
#pragma unroll
            for (int cc = 0; cc < 4; cc++) p[i][cc] = 0.f;
#pragma unroll
        for (int i = 0; i < 8; i++)
#pragma unroll
            for (int j = 0; j < 8; j++)
#pragma unroll
                for (int cc = 0; cc < 4; cc++)
                    p[i][cc] += acc[i][j] * w[j][cc];
#pragma unroll
        for (int o = 1; o < 16; o <<= 1)
#pragma unroll
            for (int i = 0; i < 8; i++)
#pragma unroll
                for (int cc = 0; cc < 4; cc++)
                    p[i][cc] += __shfl_xor_sync(0xffffffffu, p[i][cc], o);
        // 32 outputs per 16-lane group; each lane writes 2
#pragma unroll
        for (int t2 = 0; t2 < 2; t2++) {
            int k = tcol * 2 + t2;
            int i = k >> 2, cc = k & 3;
            int gr = row0 + trow * 8 + i;
            if (gr < N_NODES)
                out[(size_t)gr * NCLS + c0 + cc] = p[i][cc];
        }
    }
}

// ---------------------------------------------------------------------------
extern "C" void kernel_launch(void* const* d_in, const int* in_sizes, int n_in,
                              void* d_out, int out_size) {
    const float* x     = (const float*)d_in[0];
    const void*  ei    = d_in[1];
    const float* W_l   = (const float*)d_in[2];
    const float* b_l   = (const float*)d_in[3];
    const float* W_r   = (const float*)d_in[4];
    const float* W_cls = (const float*)d_in[5];
    float*       out   = (float*)d_out;

    const int smem_bytes = (256 * HID + 2 * KC * AS_LD + HID * NCLS + HID + TM + 32) * 4;
    cudaFuncSetAttribute(k_fused, cudaFuncAttributeMaxDynamicSharedMemorySize, smem_bytes);

    k_detect<<<1, 32>>>(ei);
    k_zero<<<2048, 256>>>();

    long long scatter_threads = (long long)NEDGE * 32;
    k_scatter<<<(int)((scatter_threads + 255) / 256), 256>>>(x, ei);

    int blocks = (N_NODES + TM - 1) / TM;
    k_fused<<<blocks, 256, smem_bytes>>>(x, W_l, b_l, W_r, W_cls, out);
}

// round 6
// speedup vs baseline: 1.9893x; 1.3936x over previous
#include <cuda_runtime.h>
#include <cuda_bf16.h>
#include <cstdint>

#define N_NODES 100000
#define HID 128
#define NCLS 20
#define NEDGE 625000
#define TM 128

// ---- smem byte offsets ----
#define SM_A      0                        // 2 bufs x (hi 16KB + lo 16KB) = 64KB
#define SM_B      (SM_A + 65536)           // hi 64KB + lo 64KB = 128KB (full K=256)
#define SM_WN     (SM_B + 131072)          // fp32 [128][20] = 10240
#define SM_BS     (SM_WN + 10240)          // fp32 [128] bias
#define SM_RC     (SM_BS + 512)            // fp32 [128] 1/max(cnt,1)
#define SM_NV     (SM_RC + 512)            // fp32 [32] W_cls col inv-norms
#define SM_SP     (SM_NV + 128)            // fp32 [2][128] row-sumsq halves
#define SM_HP     (SM_SP + 1024)           // fp32 [2][128][20] classifier halves
#define SM_TOTAL  (SM_HP + 20480)          // 229504 B (< 232448 opt-in limit)

// Scratch (device globals: allocation-free per harness rules)
__device__ float g_sum[(size_t)N_NODES * HID];
__device__ float g_cnt[N_NODES];
__device__ int   g_is64;

// ============================ PTX helpers (sm_80+ ISA only) ============================
__device__ __forceinline__ uint32_t smem_u32(const void* p) {
    uint32_t a;
    asm("{ .reg .u64 t; cvta.to.shared.u64 t, %1; cvt.u32.u64 %0, t; }"
        : "=r"(a) : "l"(p));
    return a;
}
__device__ __forceinline__ void ldsm_x4(uint32_t* r, uint32_t addr) {
    asm volatile("ldmatrix.sync.aligned.m8n8.x4.shared.b16 {%0,%1,%2,%3}, [%4];"
                 : "=r"(r[0]), "=r"(r[1]), "=r"(r[2]), "=r"(r[3]) : "r"(addr));
}
__device__ __forceinline__ void ldsm_x4_t(uint32_t* r, uint32_t addr) {
    asm volatile("ldmatrix.sync.aligned.m8n8.x4.trans.shared.b16 {%0,%1,%2,%3}, [%4];"
                 : "=r"(r[0]), "=r"(r[1]), "=r"(r[2]), "=r"(r[3]) : "r"(addr));
}
__device__ __forceinline__ void mma_bf16(float* d, const uint32_t* a,
                                         uint32_t b0, uint32_t b1) {
    asm volatile("mma.sync.aligned.m16n8k16.row.col.f32.bf16.bf16.f32 "
                 "{%0,%1,%2,%3}, {%4,%5,%6,%7}, {%8,%9}, {%0,%1,%2,%3};"
                 : "+f"(d[0]), "+f"(d[1]), "+f"(d[2]), "+f"(d[3])
                 : "r"(a[0]), "r"(a[1]), "r"(a[2]), "r"(a[3]), "r"(b0), "r"(b1));
}

// ============================ misc kernels ============================
__global__ void k_detect(const void* __restrict__ ei_raw) {
    const long long* e64 = (const long long*)ei_raw;
    int lane = threadIdx.x & 31;
    int ok = 0;
#pragma unroll
    for (int i = 0; i < 8; i++) {
        long long v = e64[lane * 8 + i];
        ok += (v >= 0 && v < N_NODES) ? 1 : 0;
    }
#pragma unroll
    for (int o = 16; o; o >>= 1) ok += __shfl_xor_sync(0xffffffffu, ok, o);
    if (lane == 0) g_is64 = (ok >= 250) ? 1 : 0;
}

__global__ void k_zero() {
    int tid = blockIdx.x * blockDim.x + threadIdx.x;
    int stride = gridDim.x * blockDim.x;
    float4 z = make_float4(0.f, 0.f, 0.f, 0.f);
    float4* s4 = reinterpret_cast<float4*>(g_sum);
    const int n4 = N_NODES * HID / 4;
    for (int i = tid; i < n4; i += stride) s4[i] = z;
    for (int i = tid; i < N_NODES; i += stride) g_cnt[i] = 0.f;
}

__global__ void k_scatter(const float* __restrict__ x,
                          const void* __restrict__ ei_raw) {
    int gtid = blockIdx.x * blockDim.x + threadIdx.x;
    int e = gtid >> 5;
    int lane = threadIdx.x & 31;
    if (e >= NEDGE) return;
    long long s = 0, d = 0;
    if (lane == 0) {
        if (g_is64) {
            const long long* e64 = (const long long*)ei_raw;
            s = e64[e]; d = e64[NEDGE + e];
        } else {
            const int* e32 = (const int*)ei_raw;
            s = e32[e]; d = e32[NEDGE + e];
        }
    }
    s = __shfl_sync(0xffffffffu, s, 0);
    d = __shfl_sync(0xffffffffu, d, 0);
    if (s < 0 || s >= N_NODES || d < 0 || d >= N_NODES) return;
    float4 v = *reinterpret_cast<const float4*>(&x[(size_t)s * HID + lane * 4]);
    float* p = &g_sum[(size_t)d * HID + lane * 4];
    asm volatile("red.global.add.v4.f32 [%0], {%1, %2, %3, %4};"
                 :: "l"(p), "f"(v.x), "f"(v.y), "f"(v.z), "f"(v.w) : "memory");
    if (lane == 0) atomicAdd(&g_cnt[d], 1.0f);
}

// ============================ fused MMA kernel ============================
// A[m][k] row-major bf16 hi/lo, 128B rows, swizzle: off ^ ((off>>3)&0x70)
// B[k][n] row-major bf16 hi/lo, 256B rows, swizzle: off ^ ((off>>4)&0x70)

__device__ __forceinline__ void store_split4(char* hi_base, char* lo_base,
                                             uint32_t off, float4 v) {
    __nv_bfloat16 h0 = __float2bfloat16(v.x), h1 = __float2bfloat16(v.y);
    __nv_bfloat16 h2 = __float2bfloat16(v.z), h3 = __float2bfloat16(v.w);
    __nv_bfloat16 l0 = __float2bfloat16(v.x - __bfloat162float(h0));
    __nv_bfloat16 l1 = __float2bfloat16(v.y - __bfloat162float(h1));
    __nv_bfloat16 l2 = __float2bfloat16(v.z - __bfloat162float(h2));
    __nv_bfloat16 l3 = __float2bfloat16(v.w - __bfloat162float(h3));
    uint32_t sw = off ^ ((off >> 3) & 0x70);
    __nv_bfloat162 hp0, hp1, lp0, lp1;
    hp0.x = h0; hp0.y = h1; hp1.x = h2; hp1.y = h3;
    lp0.x = l0; lp0.y = l1; lp1.x = l2; lp1.y = l3;
    uint2 hw, lw;
    hw.x = *(uint32_t*)&hp0; hw.y = *(uint32_t*)&hp1;
    lw.x = *(uint32_t*)&lp0; lw.y = *(uint32_t*)&lp1;
    *(uint2*)(hi_base + sw) = hw;
    *(uint2*)(lo_base + sw) = lw;
}

// prefetch A chunk c sources into regs
__device__ __forceinline__ void fetch_a(float4* pf, int c, int row0,
                                        const float* __restrict__ x,
                                        const float* __restrict__ rc) {
    const int tid = threadIdx.x;
#pragma unroll
    for (int i = 0; i < 8; i++) {
        int idx = tid + i * 256;          // 128 rows x 16 k-quads
        int row = idx >> 4, q = idx & 15;
        int r = row0 + row;
        float4 v = make_float4(0.f, 0.f, 0.f, 0.f);
        if (r < N_NODES) {
            if (c < 2) {
                float sc = rc[row];
                float4 t = *(const float4*)&g_sum[(size_t)r * HID + c * 64 + q * 4];
                v.x = t.x * sc; v.y = t.y * sc; v.z = t.z * sc; v.w = t.w * sc;
            } else {
                v = *(const float4*)&x[(size_t)r * HID + (c - 2) * 64 + q * 4];
            }
        }
        pf[i] = v;
    }
}

__device__ __forceinline__ void store_a(char* smem, const float4* pf, int c) {
    const int tid = threadIdx.x;
    char* hi = smem + SM_A + (c & 1) * 32768;
    char* lo = hi + 16384;
#pragma unroll
    for (int i = 0; i < 8; i++) {
        int idx = tid + i * 256;
        int row = idx >> 4, q = idx & 15;
        store_split4(hi, lo, (uint32_t)(row * 128 + q * 8), pf[i]);
    }
}

__device__ __forceinline__ void load_b_full(char* smem,
                                            const float* __restrict__ W_l,
                                            const float* __restrict__ W_r) {
    const int tid = threadIdx.x;
    char* hi = smem + SM_B;
    char* lo = hi + 65536;
#pragma unroll
    for (int i = 0; i < 32; i++) {
        int idx = tid + i * 256;          // 256 k-rows x 32 n-quads
        int k = idx >> 5, n0 = (idx & 31) * 4;
        float4 v = (k < 128)
            ? *(const float4*)&W_l[(size_t)k * HID + n0]
            : *(const float4*)&W_r[(size_t)(k - 128) * HID + n0];
        __nv_bfloat16 h0 = __float2bfloat16(v.x), h1 = __float2bfloat16(v.y);
        __nv_bfloat16 h2 = __float2bfloat16(v.z), h3 = __float2bfloat16(v.w);
        __nv_bfloat16 l0 = __float2bfloat16(v.x - __bfloat162float(h0));
        __nv_bfloat16 l1 = __float2bfloat16(v.y - __bfloat162float(h1));
        __nv_bfloat16 l2 = __float2bfloat16(v.z - __bfloat162float(h2));
        __nv_bfloat16 l3 = __float2bfloat16(v.w - __bfloat162float(h3));
        uint32_t off = (uint32_t)(k * 256 + n0 * 2);
        uint32_t sw = off ^ ((off >> 4) & 0x70);
        __nv_bfloat162 hp0, hp1, lp0, lp1;
        hp0.x = h0; hp0.y = h1; hp1.x = h2; hp1.y = h3;
        lp0.x = l0; lp0.y = l1; lp1.x = l2; lp1.y = l3;
        uint2 hw, lw;
        hw.x = *(uint32_t*)&hp0; hw.y = *(uint32_t*)&hp1;
        lw.x = *(uint32_t*)&lp0; lw.y = *(uint32_t*)&lp1;
        *(uint2*)(hi + sw) = hw;
        *(uint2*)(lo + sw) = lw;
    }
}

__global__ void __launch_bounds__(256, 1)
k_fused(const float* __restrict__ x,
        const float* __restrict__ W_l,
        const float* __restrict__ b_l,
        const float* __restrict__ W_r,
        const float* __restrict__ W_cls,
        float* __restrict__ out) {
    extern __shared__ __align__(1024) char smem[];
    const uint32_t sbase = smem_u32(smem);
    const int tid  = threadIdx.x;
    const int wid  = tid >> 5;
    const int lane = tid & 31;
    const int row0 = blockIdx.x * TM;
    const int wm = wid & 3;               // warp M coordinate (4)
    const int wn = wid >> 2;              // warp N coordinate (2)

    float* Wn = (float*)(smem + SM_WN);
    float* bs = (float*)(smem + SM_BS);
    float* rc = (float*)(smem + SM_RC);
    float* nv = (float*)(smem + SM_NV);
    float* Sp = (float*)(smem + SM_SP);
    float* Hp = (float*)(smem + SM_HP);

    // ---- phase A: small tables ----
    if (tid < 128) {
        bs[tid] = b_l[tid];
        int r = row0 + tid;
        rc[tid] = (r < N_NODES) ? 1.0f / fmaxf(g_cnt[r], 1.0f) : 0.0f;
    }
    for (int i = tid; i < HID * NCLS; i += 256) Wn[i] = W_cls[i];
    __syncthreads();                                       // S1

    // ---- stage chunk 0 + full B; nv overlapped ----
    {
        float4 pf0[8];
        fetch_a(pf0, 0, row0, x, rc);
        store_a(smem, pf0, 0);
    }
    load_b_full(smem, W_l, W_r);
    if (tid < NCLS) {
        float ss = 0.f;
        for (int j = 0; j < HID; j++) { float v = Wn[j * NCLS + tid]; ss += v * v; }
        nv[tid] = 1.0f / fmaxf(sqrtf(ss), 1e-12f);
    }
    __syncthreads();                                       // S2
    // scale W_cls columns now (epilogue reads after later syncs)
    for (int i = tid; i < HID * NCLS; i += 256) Wn[i] *= nv[i % NCLS];

    // ---- main GEMM: 4 chunks of K=64, 3-pass split bf16 ----
    float acc[2][8][4];
#pragma unroll
    for (int i = 0; i < 2; i++)
#pragma unroll
        for (int j = 0; j < 8; j++)
#pragma unroll
            for (int p = 0; p < 4; p++) acc[i][j][p] = 0.f;

    const int lane15 = lane & 15, laneh = lane >> 4;
    const int bg = lane >> 3, brr = lane & 7;

    float4 pf[8];
    for (int c = 0; c < 4; c++) {
        if (c < 3) fetch_a(pf, c + 1, row0, x, rc);

        const uint32_t abase = sbase + SM_A + (c & 1) * 32768;
        const uint32_t bbase = sbase + SM_B;
#pragma unroll
        for (int ks = 0; ks < 4; ks++) {
            // A fragments (2 m-tiles, hi+lo)
            uint32_t ah[2][4], al[2][4];
#pragma unroll
            for (int i = 0; i < 2; i++) {
                uint32_t off = (uint32_t)((wm * 32 + i * 16 + lane15) * 128
                                          + ks * 32 + laneh * 16);
                uint32_t sw = off ^ ((off >> 3) & 0x70);
                ldsm_x4(ah[i], abase + sw);
                ldsm_x4(al[i], abase + 16384 + sw);
            }
            // B fragments: 4 x4.trans -> 8 n-tiles, hi+lo
            uint32_t bh[4][4], bl[4][4];
            int krow = c * 64 + ks * 16 + (bg & 1) * 8 + brr;
            int nof = (bg >> 1) * 16;
#pragma unroll
            for (int j2 = 0; j2 < 4; j2++) {
                uint32_t off = (uint32_t)(krow * 256 + wn * 128 + j2 * 32 + nof);
                uint32_t sw = off ^ ((off >> 4) & 0x70);
                ldsm_x4_t(bh[j2], bbase + sw);
                ldsm_x4_t(bl[j2], bbase + 65536 + sw);
            }
            // 3 passes: hi*hi, lo*hi, hi*lo
#pragma unroll
            for (int i = 0; i < 2; i++)
#pragma unroll
                for (int j = 0; j < 8; j++) {
                    const uint32_t* Bh = &bh[j >> 1][(j & 1) * 2];
                    const uint32_t* Bl = &bl[j >> 1][(j & 1) * 2];
                    mma_bf16(acc[i][j], ah[i], Bh[0], Bh[1]);
                    mma_bf16(acc[i][j], al[i], Bh[0], Bh[1]);
                    mma_bf16(acc[i][j], ah[i], Bl[0], Bl[1]);
                }
        }
        if (c < 3) {
            store_a(smem, pf, c + 1);
            __syncthreads();
        }
    }

    // ---- epilogue: bias + row L2 partials + classifier partials (registers) ----
    // C frag map: d0:(r=lane>>2, c=(lane&3)*2) d1:(r,c+1) d2:(r+8,c) d3:(r+8,c+1)
#pragma unroll
    for (int i = 0; i < 2; i++) {
#pragma unroll
        for (int rr2 = 0; rr2 < 2; rr2++) {
            int row = wm * 32 + i * 16 + (lane >> 2) + rr2 * 8;
            float h[16];
            float ss = 0.f;
#pragma unroll
            for (int j = 0; j < 8; j++)
#pragma unroll
                for (int p = 0; p < 2; p++) {
                    int colloc = j * 8 + (lane & 3) * 2 + p;
                    float v = acc[i][j][rr2 * 2 + p] + bs[wn * 64 + colloc];
                    h[j * 2 + p] = v;
                    ss += v * v;
                }
            ss += __shfl_xor_sync(0xffffffffu, ss, 1);
            ss += __shfl_xor_sync(0xffffffffu, ss, 2);

            float pc[NCLS];
#pragma unroll
            for (int cc = 0; cc < NCLS; cc++) pc[cc] = 0.f;
#pragma unroll
            for (int jj = 0; jj < 16; jj++) {
                int col = wn * 64 + (jj >> 1) * 8 + (lane & 3) * 2 + (jj & 1);
                float v = h[jj];
                const float* wr = &Wn[col * NCLS];
#pragma unroll
                for (int cc = 0; cc < NCLS; cc++) pc[cc] += v * wr[cc];
            }
#pragma unroll
            for (int cc = 0; cc < NCLS; cc++) {
                pc[cc] += __shfl_xor_sync(0xffffffffu, pc[cc], 1);
                pc[cc] += __shfl_xor_sync(0xffffffffu, pc[cc], 2);
            }
            if ((lane & 3) == 0) {
                Sp[wn * 128 + row] = ss;
                float* hp = &Hp[(wn * 128 + row) * NCLS];
#pragma unroll
                for (int cc = 0; cc < NCLS; cc++) hp[cc] = pc[cc];
            }
        }
    }
    __syncthreads();

    // ---- combine halves + write ----
    for (int i = tid; i < TM * NCLS; i += 256) {
        int r = i / NCLS, cc = i % NCLS;
        int gr = row0 + r;
        if (gr >= N_NODES) continue;
        float ssum = Sp[r] + Sp[128 + r];
        float rinv = 1.0f / fmaxf(sqrtf(ssum), 1e-12f);
        out[(size_t)gr * NCLS + cc] = (Hp[r * NCLS + cc] + Hp[(128 + r) * NCLS + cc]) * rinv;
    }
}

// ---------------------------------------------------------------------------
extern "C" void kernel_launch(void* const* d_in, const int* in_sizes, int n_in,
                              void* d_out, int out_size) {
    const float* x     = (const float*)d_in[0];
    const void*  ei    = d_in[1];
    const float* W_l   = (const float*)d_in[2];
    const float* b_l   = (const float*)d_in[3];
    const float* W_r   = (const float*)d_in[4];
    const float* W_cls = (const float*)d_in[5];
    float*       out   = (float*)d_out;

    cudaFuncSetAttribute(k_fused, cudaFuncAttributeMaxDynamicSharedMemorySize, SM_TOTAL);

    k_detect<<<1, 32>>>(ei);
    k_zero<<<2048, 256>>>();

    long long scatter_threads = (long long)NEDGE * 32;
    k_scatter<<<(int)((scatter_threads + 255) / 256), 256>>>(x, ei);

    int blocks = (N_NODES + TM - 1) / TM;
    k_fused<<<blocks, 256, SM_TOTAL>>>(x, W_l, b_l, W_r, W_cls, out);
}

// round 8
// speedup vs baseline: 2.2247x; 1.1184x over previous
#include <cuda_runtime.h>
#include <cuda_bf16.h>
#include <cstdint>

#define N_NODES 100000
#define HID 128
#define NCLS 20
#define NEDGE 625000
#define TM 128

// ---- smem byte offsets ----
#define SM_A      0                        // 2 bufs x (hi 16KB + lo 16KB) = 64KB
#define SM_B      (SM_A + 65536)           // hi 64KB + lo 64KB (pre-swizzled image)
#define SM_WN     (SM_B + 131072)          // fp32 [128][20] (pre-normalized)
#define SM_BS     (SM_WN + 10240)          // fp32 [128] bias
#define SM_RC     (SM_BS + 512)            // fp32 [128] 1/max(cnt,1)
#define SM_SP     (SM_RC + 512)            // fp32 [2][128] row-sumsq halves
#define SM_HP     (SM_SP + 1024)           // fp32 [2][128][20] classifier halves
#define SM_TOTAL  (SM_HP + 20480)          // 229376 B

// Scratch (device globals: allocation-free per harness rules)
__device__ float g_sum[(size_t)N_NODES * HID];
__device__ float g_cnt[N_NODES];
__device__ int   g_is64;
__device__ __align__(16) unsigned char g_Bprep[131072];  // pre-swizzled bf16 hi|lo
__device__ float g_Wn[HID * NCLS];                       // pre-normalized W_cls

// ============================ PTX helpers (sm_80+ ISA only) ============================
__device__ __forceinline__ uint32_t smem_u32(const void* p) {
    uint32_t a;
    asm("{ .reg .u64 t; cvta.to.shared.u64 t, %1; cvt.u32.u64 %0, t; }"
        : "=r"(a) : "l"(p));
    return a;
}
__device__ __forceinline__ void ldsm_x4(uint32_t* r, uint32_t addr) {
    asm volatile("ldmatrix.sync.aligned.m8n8.x4.shared.b16 {%0,%1,%2,%3}, [%4];"
                 : "=r"(r[0]), "=r"(r[1]), "=r"(r[2]), "=r"(r[3]) : "r"(addr));
}
__device__ __forceinline__ void ldsm_x4_t(uint32_t* r, uint32_t addr) {
    asm volatile("ldmatrix.sync.aligned.m8n8.x4.trans.shared.b16 {%0,%1,%2,%3}, [%4];"
                 : "=r"(r[0]), "=r"(r[1]), "=r"(r[2]), "=r"(r[3]) : "r"(addr));
}
__device__ __forceinline__ void mma_bf16(float* d, const uint32_t* a,
                                         uint32_t b0, uint32_t b1) {
    asm volatile("mma.sync.aligned.m16n8k16.row.col.f32.bf16.bf16.f32 "
                 "{%0,%1,%2,%3}, {%4,%5,%6,%7}, {%8,%9}, {%0,%1,%2,%3};"
                 : "+f"(d[0]), "+f"(d[1]), "+f"(d[2]), "+f"(d[3])
                 : "r"(a[0]), "r"(a[1]), "r"(a[2]), "r"(a[3]), "r"(b0), "r"(b1));
}
__device__ __forceinline__ void cp_async16(uint32_t dst, const void* src) {
    asm volatile("cp.async.cg.shared.global [%0], [%1], 16;" :: "r"(dst), "l"(src));
}
#define CP_COMMIT() asm volatile("cp.async.commit_group;" ::: "memory")
#define CP_WAIT0()  asm volatile("cp.async.wait_group 0;" ::: "memory")

// ============================ misc kernels ============================
__global__ void k_detect(const void* __restrict__ ei_raw) {
    const long long* e64 = (const long long*)ei_raw;
    int lane = threadIdx.x & 31;
    int ok = 0;
#pragma unroll
    for (int i = 0; i < 8; i++) {
        long long v = e64[lane * 8 + i];
        ok += (v >= 0 && v < N_NODES) ? 1 : 0;
    }
#pragma unroll
    for (int o = 16; o; o >>= 1) ok += __shfl_xor_sync(0xffffffffu, ok, o);
    if (lane == 0) g_is64 = (ok >= 250) ? 1 : 0;
}

__global__ void k_zero() {
    int tid = blockIdx.x * blockDim.x + threadIdx.x;
    int stride = gridDim.x * blockDim.x;
    float4 z = make_float4(0.f, 0.f, 0.f, 0.f);
    float4* s4 = reinterpret_cast<float4*>(g_sum);
    const int n4 = N_NODES * HID / 4;
    for (int i = tid; i < n4; i += stride) s4[i] = z;
    for (int i = tid; i < N_NODES; i += stride) g_cnt[i] = 0.f;
}

__global__ void k_scatter(const float* __restrict__ x,
                          const void* __restrict__ ei_raw) {
    int gtid = blockIdx.x * blockDim.x + threadIdx.x;
    int e = gtid >> 5;
    int lane = threadIdx.x & 31;
    if (e >= NEDGE) return;
    long long s = 0, d = 0;
    if (lane == 0) {
        if (g_is64) {
            const long long* e64 = (const long long*)ei_raw;
            s = e64[e]; d = e64[NEDGE + e];
        } else {
            const int* e32 = (const int*)ei_raw;
            s = e32[e]; d = e32[NEDGE + e];
        }
    }
    s = __shfl_sync(0xffffffffu, s, 0);
    d = __shfl_sync(0xffffffffu, d, 0);
    if (s < 0 || s >= N_NODES || d < 0 || d >= N_NODES) return;
    float4 v = *reinterpret_cast<const float4*>(&x[(size_t)s * HID + lane * 4]);
    float* p = &g_sum[(size_t)d * HID + lane * 4];
    asm volatile("red.global.add.v4.f32 [%0], {%1, %2, %3, %4};"
                 :: "l"(p), "f"(v.x), "f"(v.y), "f"(v.z), "f"(v.w) : "memory");
    if (lane == 0) atomicAdd(&g_cnt[d], 1.0f);
}

// ---- one-shot weight prep: B (concat W_l/W_r) -> pre-swizzled bf16 hi/lo ----
__global__ void k_prep(const float* __restrict__ W_l,
                       const float* __restrict__ W_r) {
    int idx = blockIdx.x * blockDim.x + threadIdx.x;   // 8192 quads
    if (idx >= 8192) return;
    int k = idx >> 5, n0 = (idx & 31) * 4;
    float4 v = (k < 128)
        ? *(const float4*)&W_l[(size_t)k * HID + n0]
        : *(const float4*)&W_r[(size_t)(k - 128) * HID + n0];
    __nv_bfloat16 h0 = __float2bfloat16(v.x), h1 = __float2bfloat16(v.y);
    __nv_bfloat16 h2 = __float2bfloat16(v.z), h3 = __float2bfloat16(v.w);
    __nv_bfloat16 l0 = __float2bfloat16(v.x - __bfloat162float(h0));
    __nv_bfloat16 l1 = __float2bfloat16(v.y - __bfloat162float(h1));
    __nv_bfloat16 l2 = __float2bfloat16(v.z - __bfloat162float(h2));
    __nv_bfloat16 l3 = __float2bfloat16(v.w - __bfloat162float(h3));
    uint32_t off = (uint32_t)(k * 256 + n0 * 2);
    uint32_t sw = off ^ ((off >> 4) & 0x70);
    __nv_bfloat162 hp0, hp1, lp0, lp1;
    hp0.x = h0; hp0.y = h1; hp1.x = h2; hp1.y = h3;
    lp0.x = l0; lp0.y = l1; lp1.x = l2; lp1.y = l3;
    uint2 hw, lw;
    hw.x = *(uint32_t*)&hp0; hw.y = *(uint32_t*)&hp1;
    lw.x = *(uint32_t*)&lp0; lw.y = *(uint32_t*)&lp1;
    *(uint2*)(g_Bprep + sw)         = hw;
    *(uint2*)(g_Bprep + 65536 + sw) = lw;
}

// ---- one-shot classifier prep: g_Wn = W_cls * colnorm^-1 ----
__global__ void k_prepw(const float* __restrict__ W_cls) {
    __shared__ float nv[NCLS];
    int tid = threadIdx.x;
    if (tid < NCLS) {
        float ss = 0.f;
        for (int j = 0; j < HID; j++) { float v = W_cls[j * NCLS + tid]; ss += v * v; }
        nv[tid] = 1.0f / fmaxf(sqrtf(ss), 1e-12f);
    }
    __syncthreads();
    for (int i = tid; i < HID * NCLS; i += blockDim.x)
        g_Wn[i] = W_cls[i] * nv[i % NCLS];
}

// ============================ fused MMA kernel ============================
// A[m][k] row-major bf16 hi/lo, 128B rows, swizzle: off ^ ((off>>3)&0x70)
// B[k][n] row-major bf16 hi/lo, 256B rows, swizzle: off ^ ((off>>4)&0x70)

__device__ __forceinline__ void store_split4(char* hi_base, char* lo_base,
                                             uint32_t off, float4 v) {
    __nv_bfloat16 h0 = __float2bfloat16(v.x), h1 = __float2bfloat16(v.y);
    __nv_bfloat16 h2 = __float2bfloat16(v.z), h3 = __float2bfloat16(v.w);
    __nv_bfloat16 l0 = __float2bfloat16(v.x - __bfloat162float(h0));
    __nv_bfloat16 l1 = __float2bfloat16(v.y - __bfloat162float(h1));
    __nv_bfloat16 l2 = __float2bfloat16(v.z - __bfloat162float(h2));
    __nv_bfloat16 l3 = __float2bfloat16(v.w - __bfloat162float(h3));
    uint32_t sw = off ^ ((off >> 3) & 0x70);
    __nv_bfloat162 hp0, hp1, lp0, lp1;
    hp0.x = h0; hp0.y = h1; hp1.x = h2; hp1.y = h3;
    lp0.x = l0; lp0.y = l1; lp1.x = l2; lp1.y = l3;
    uint2 hw, lw;
    hw.x = *(uint32_t*)&hp0; hw.y = *(uint32_t*)&hp1;
    lw.x = *(uint32_t*)&lp0; lw.y = *(uint32_t*)&lp1;
    *(uint2*)(hi_base + sw) = hw;
    *(uint2*)(lo_base + sw) = lw;
}

__device__ __forceinline__ void fetch_a(float4* pf, int c, int row0,
                                        const float* __restrict__ x,
                                        const float* __restrict__ rc) {
    const int tid = threadIdx.x;
#pragma unroll
    for (int i = 0; i < 4; i++) {
        int idx = tid + i * 512;          // 128 rows x 16 k-quads
        int row = idx >> 4, q = idx & 15;
        int r = row0 + row;
        float4 v = make_float4(0.f, 0.f, 0.f, 0.f);
        if (r < N_NODES) {
            if (c < 2) {
                float sc = rc[row];
                float4 t = *(const float4*)&g_sum[(size_t)r * HID + c * 64 + q * 4];
                v.x = t.x * sc; v.y = t.y * sc; v.z = t.z * sc; v.w = t.w * sc;
            } else {
                v = *(const float4*)&x[(size_t)r * HID + (c - 2) * 64 + q * 4];
            }
        }
        pf[i] = v;
    }
}

__device__ __forceinline__ void store_a(char* smem, const float4* pf, int c) {
    const int tid = threadIdx.x;
    char* hi = smem + SM_A + (c & 1) * 32768;
    char* lo = hi + 16384;
#pragma unroll
    for (int i = 0; i < 4; i++) {
        int idx = tid + i * 512;
        int row = idx >> 4, q = idx & 15;
        store_split4(hi, lo, (uint32_t)(row * 128 + q * 8), pf[i]);
    }
}

__global__ void __launch_bounds__(512, 1)
k_fused(const float* __restrict__ x,
        const float* __restrict__ b_l,
        float* __restrict__ out) {
    extern __shared__ __align__(1024) char smem[];
    const uint32_t sbase = smem_u32(smem);
    const int tid  = threadIdx.x;
    const int wid  = tid >> 5;
    const int lane = tid & 31;
    const int row0 = blockIdx.x * TM;
    const int wm = wid & 7;               // warp M coordinate (8): rows wm*16..+15
    const int wn = wid >> 3;              // warp N coordinate (2): cols wn*64..+63

    float* Wn = (float*)(smem + SM_WN);
    float* bs = (float*)(smem + SM_BS);
    float* rc = (float*)(smem + SM_RC);
    float* Sp = (float*)(smem + SM_SP);
    float* Hp = (float*)(smem + SM_HP);

    // ---- B image via cp.async (pre-swizzled, no conversion) ----
#pragma unroll
    for (int i = 0; i < 16; i++) {
        uint32_t off = (uint32_t)(tid + i * 512) * 16;
        cp_async16(sbase + SM_B + off, g_Bprep + off);
    }
    CP_COMMIT();

    // ---- small tables ----
    if (tid < 128) {
        bs[tid] = b_l[tid];
        int r = row0 + tid;
        rc[tid] = (r < N_NODES) ? 1.0f / fmaxf(g_cnt[r], 1.0f) : 0.0f;
    }
    for (int i = tid; i < HID * NCLS; i += 512) Wn[i] = g_Wn[i];
    __syncthreads();                                       // S1 (rc visible)

    // ---- stage chunk 0 ----
    {
        float4 pf0[4];
        fetch_a(pf0, 0, row0, x, rc);
        store_a(smem, pf0, 0);
    }
    CP_WAIT0();
    __syncthreads();                                       // S2

    // ---- main GEMM: 4 chunks of K=64, 3-pass split bf16 ----
    float acc[8][4];
#pragma unroll
    for (int j = 0; j < 8; j++)
#pragma unroll
        for (int p = 0; p < 4; p++) acc[j][p] = 0.f;

    const int lane15 = lane & 15, laneh = lane >> 4;
    const int bg = lane >> 3, brr = lane & 7;

    float4 pf[4];
    for (int c = 0; c < 4; c++) {
        if (c < 3) fetch_a(pf, c + 1, row0, x, rc);

        const uint32_t abase = sbase + SM_A + (c & 1) * 32768;
        const uint32_t bbase = sbase + SM_B;
#pragma unroll
        for (int ks = 0; ks < 4; ks++) {
            // A fragments (1 m-tile of 16 rows, hi+lo)
            uint32_t ah[4], al[4];
            {
                uint32_t off = (uint32_t)((wm * 16 + lane15) * 128
                                          + ks * 32 + laneh * 16);
                uint32_t sw = off ^ ((off >> 3) & 0x70);
                ldsm_x4(ah, abase + sw);
                ldsm_x4(al, abase + 16384 + sw);
            }
            // B fragments: 4 x4.trans -> 8 n-tiles, hi+lo
            uint32_t bh[4][4], bl[4][4];
            int krow = c * 64 + ks * 16 + (bg & 1) * 8 + brr;
            int nof = (bg >> 1) * 16;
#pragma unroll
            for (int j2 = 0; j2 < 4; j2++) {
                uint32_t off = (uint32_t)(krow * 256 + wn * 128 + j2 * 32 + nof);
                uint32_t sw = off ^ ((off >> 4) & 0x70);
                ldsm_x4_t(bh[j2], bbase + sw);
                ldsm_x4_t(bl[j2], bbase + 65536 + sw);
            }
            // 3 passes: hi*hi, lo*hi, hi*lo
#pragma unroll
            for (int j = 0; j < 8; j++) {
                const uint32_t* Bh = &bh[j >> 1][(j & 1) * 2];
                const uint32_t* Bl = &bl[j >> 1][(j & 1) * 2];
                mma_bf16(acc[j], ah, Bh[0], Bh[1]);
                mma_bf16(acc[j], al, Bh[0], Bh[1]);
                mma_bf16(acc[j], ah, Bl[0], Bl[1]);
            }
        }
        if (c < 3) {
            store_a(smem, pf, c + 1);
            __syncthreads();
        }
    }

    // ---- epilogue: bias + row L2 partials + classifier partials (registers) ----
    // C frag map: d0:(r=lane>>2, c=(lane&3)*2) d1:(r,c+1) d2:(r+8,c) d3:(r+8,c+1)
#pragma unroll
    for (int rr2 = 0; rr2 < 2; rr2++) {
        int row = wm * 16 + (lane >> 2) + rr2 * 8;
        float h[16];
        float ss = 0.f;
#pragma unroll
        for (int j = 0; j < 8; j++)
#pragma unroll
            for (int p = 0; p < 2; p++) {
                int colloc = j * 8 + (lane & 3) * 2 + p;
                float v = acc[j][rr2 * 2 + p] + bs[wn * 64 + colloc];
                h[j * 2 + p] = v;
                ss += v * v;
            }
        ss += __shfl_xor_sync(0xffffffffu, ss, 1);
        ss += __shfl_xor_sync(0xffffffffu, ss, 2);

        float pc[NCLS];
#pragma unroll
        for (int cc = 0; cc < NCLS; cc++) pc[cc] = 0.f;
#pragma unroll
        for (int jj = 0; jj < 16; jj++) {
            int col = wn * 64 + (jj >> 1) * 8 + (lane & 3) * 2 + (jj & 1);
            float v = h[jj];
            const float* wr = &Wn[col * NCLS];
#pragma unroll
            for (int cc = 0; cc < NCLS; cc++) pc[cc] += v * wr[cc];
        }
#pragma unroll
        for (int cc = 0; cc < NCLS; cc++) {
            pc[cc] += __shfl_xor_sync(0xffffffffu, pc[cc], 1);
            pc[cc] += __shfl_xor_sync(0xffffffffu, pc[cc], 2);
        }
        if ((lane & 3) == 0) {
            Sp[wn * 128 + row] = ss;
            float* hp = &Hp[(wn * 128 + row) * NCLS];
#pragma unroll
            for (int cc = 0; cc < NCLS; cc++) hp[cc] = pc[cc];
        }
    }
    __syncthreads();

    // ---- combine halves + write ----
    for (int i = tid; i < TM * NCLS; i += 512) {
        int r = i / NCLS, cc = i % NCLS;
        int gr = row0 + r;
        if (gr >= N_NODES) continue;
        float ssum = Sp[r] + Sp[128 + r];
        float rinv = 1.0f / fmaxf(sqrtf(ssum), 1e-12f);
        out[(size_t)gr * NCLS + cc] = (Hp[r * NCLS + cc] + Hp[(128 + r) * NCLS + cc]) * rinv;
    }
}

// ---------------------------------------------------------------------------
extern "C" void kernel_launch(void* const* d_in, const int* in_sizes, int n_in,
                              void* d_out, int out_size) {
    const float* x     = (const float*)d_in[0];
    const void*  ei    = d_in[1];
    const float* W_l   = (const float*)d_in[2];
    const float* b_l   = (const float*)d_in[3];
    const float* W_r   = (const float*)d_in[4];
    const float* W_cls = (const float*)d_in[5];
    float*       out   = (float*)d_out;

    cudaFuncSetAttribute(k_fused, cudaFuncAttributeMaxDynamicSharedMemorySize, SM_TOTAL);

    k_detect<<<1, 32>>>(ei);
    k_prep<<<16, 512>>>(W_l, W_r);
    k_prepw<<<1, 256>>>(W_cls);
    k_zero<<<2048, 256>>>();

    long long scatter_threads = (long long)NEDGE * 32;
    k_scatter<<<(int)((scatter_threads + 255) / 256), 256>>>(x, ei);

    int blocks = (N_NODES + TM - 1) / TM;
    k_fused<<<blocks, 512, SM_TOTAL>>>(x, b_l, out);
}

// round 10
// speedup vs baseline: 2.4950x; 1.1215x over previous
#include <cuda_runtime.h>
#include <cuda_bf16.h>
#include <cstdint>

#define N_NODES 100000
#define HID 128
#define NCLS 20
#define NEDGE 625000
#define TM 128
#define NTILES ((N_NODES + TM - 1) / TM)   // 782
#define GRID_F 148

// ---- smem byte offsets ----
#define SM_A      0                        // 2 bufs x (hi 16KB + lo 16KB) = 64KB
#define SM_B      (SM_A + 65536)           // hi 64KB + lo 64KB (pre-swizzled image)
#define SM_WN     (SM_B + 131072)          // fp32 [128][20] (pre-normalized)
#define SM_BS     (SM_WN + 10240)          // fp32 [128] bias
#define SM_SP     (SM_BS + 512)            // fp32 [2][128] row-sumsq halves
#define SM_HP     (SM_SP + 1024)           // fp32 [2][128][20] classifier halves
#define SM_TOTAL  (SM_HP + 20480)          // 228864 B

// Scratch (device globals: allocation-free per harness rules)
__device__ float g_sum[(size_t)N_NODES * HID];
__device__ float g_cnt[N_NODES];
__device__ int   g_is64;
__device__ __align__(16) unsigned char g_Bprep[131072];  // pre-swizzled bf16 hi|lo
__device__ float g_Wn[HID * NCLS];                       // pre-normalized W_cls

// ============================ PTX helpers (sm_80+ ISA only) ============================
__device__ __forceinline__ uint32_t smem_u32(const void* p) {
    uint32_t a;
    asm("{ .reg .u64 t; cvta.to.shared.u64 t, %1; cvt.u32.u64 %0, t; }"
        : "=r"(a) : "l"(p));
    return a;
}
__device__ __forceinline__ void ldsm_x4(uint32_t* r, uint32_t addr) {
    asm volatile("ldmatrix.sync.aligned.m8n8.x4.shared.b16 {%0,%1,%2,%3}, [%4];"
                 : "=r"(r[0]), "=r"(r[1]), "=r"(r[2]), "=r"(r[3]) : "r"(addr));
}
__device__ __forceinline__ void ldsm_x4_t(uint32_t* r, uint32_t addr) {
    asm volatile("ldmatrix.sync.aligned.m8n8.x4.trans.shared.b16 {%0,%1,%2,%3}, [%4];"
                 : "=r"(r[0]), "=r"(r[1]), "=r"(r[2]), "=r"(r[3]) : "r"(addr));
}
__device__ __forceinline__ void mma_bf16(float* d, const uint32_t* a,
                                         uint32_t b0, uint32_t b1) {
    asm volatile("mma.sync.aligned.m16n8k16.row.col.f32.bf16.bf16.f32 "
                 "{%0,%1,%2,%3}, {%4,%5,%6,%7}, {%8,%9}, {%0,%1,%2,%3};"
                 : "+f"(d[0]), "+f"(d[1]), "+f"(d[2]), "+f"(d[3])
                 : "r"(a[0]), "r"(a[1]), "r"(a[2]), "r"(a[3]), "r"(b0), "r"(b1));
}
__device__ __forceinline__ void cp_async16(uint32_t dst, const void* src) {
    asm volatile("cp.async.cg.shared.global [%0], [%1], 16;" :: "r"(dst), "l"(src));
}
#define CP_COMMIT() asm volatile("cp.async.commit_group;" ::: "memory")
#define CP_WAIT0()  asm volatile("cp.async.wait_group 0;" ::: "memory")

// ============================ init kernel: detect + prepw + prep + zero ============================
__global__ void __launch_bounds__(512)
k_init(const void* __restrict__ ei_raw,
       const float* __restrict__ W_l,
       const float* __restrict__ W_r,
       const float* __restrict__ W_cls) {
    const int b = blockIdx.x;
    const int tid = threadIdx.x;

    if (b == 0) {
        // ---- dtype detect (warp 0) ----
        if (tid < 32) {
            const long long* e64 = (const long long*)ei_raw;
            int ok = 0;
#pragma unroll
            for (int i = 0; i < 8; i++) {
                long long v = e64[tid * 8 + i];
                ok += (v >= 0 && v < N_NODES) ? 1 : 0;
            }
#pragma unroll
            for (int o = 16; o; o >>= 1) ok += __shfl_xor_sync(0xffffffffu, ok, o);
            if (tid == 0) g_is64 = (ok >= 250) ? 1 : 0;
        }
        // ---- classifier prep ----
        __shared__ float nv[NCLS];
        if (tid < NCLS) {
            float ss = 0.f;
            for (int j = 0; j < HID; j++) { float v = W_cls[j * NCLS + tid]; ss += v * v; }
            nv[tid] = 1.0f / fmaxf(sqrtf(ss), 1e-12f);
        }
        __syncthreads();
        for (int i = tid; i < HID * NCLS; i += 512)
            g_Wn[i] = W_cls[i] * nv[i % NCLS];
    } else if (b <= 16) {
        // ---- B prep: 16 blocks x 512 threads = 8192 quads ----
        int idx = (b - 1) * 512 + tid;
        int k = idx >> 5, n0 = (idx & 31) * 4;
        float4 v = (k < 128)
            ? *(const float4*)&W_l[(size_t)k * HID + n0]
            : *(const float4*)&W_r[(size_t)(k - 128) * HID + n0];
        __nv_bfloat16 h0 = __float2bfloat16(v.x), h1 = __float2bfloat16(v.y);
        __nv_bfloat16 h2 = __float2bfloat16(v.z), h3 = __float2bfloat16(v.w);
        __nv_bfloat16 l0 = __float2bfloat16(v.x - __bfloat162float(h0));
        __nv_bfloat16 l1 = __float2bfloat16(v.y - __bfloat162float(h1));
        __nv_bfloat16 l2 = __float2bfloat16(v.z - __bfloat162float(h2));
        __nv_bfloat16 l3 = __float2bfloat16(v.w - __bfloat162float(h3));
        uint32_t off = (uint32_t)(k * 256 + n0 * 2);
        uint32_t sw = off ^ ((off >> 4) & 0x70);
        __nv_bfloat162 hp0, hp1, lp0, lp1;
        hp0.x = h0; hp0.y = h1; hp1.x = h2; hp1.y = h3;
        lp0.x = l0; lp0.y = l1; lp1.x = l2; lp1.y = l3;
        uint2 hw, lw;
        hw.x = *(uint32_t*)&hp0; hw.y = *(uint32_t*)&hp1;
        lw.x = *(uint32_t*)&lp0; lw.y = *(uint32_t*)&lp1;
        *(uint2*)(g_Bprep + sw)         = hw;
        *(uint2*)(g_Bprep + 65536 + sw) = lw;
    } else {
        // ---- zero accumulators: 1024 blocks ----
        int gid = (b - 17) * 512 + tid;
        const int stride = 1024 * 512;
        float4 z = make_float4(0.f, 0.f, 0.f, 0.f);
        float4* s4 = reinterpret_cast<float4*>(g_sum);
        const int n4 = N_NODES * HID / 4;
        for (int i = gid; i < n4; i += stride) s4[i] = z;
        for (int i = gid; i < N_NODES; i += stride) g_cnt[i] = 0.f;
    }
}

// ============================ scatter: 32 edges per warp ============================
__global__ void k_scatter(const float* __restrict__ x,
                          const void* __restrict__ ei_raw) {
    const int wg   = (blockIdx.x * blockDim.x + threadIdx.x) >> 5;
    const int lane = threadIdx.x & 31;
    const int base = wg * 32;
    if (base >= NEDGE) return;

    // coalesced per-lane index load
    int sv = -1, dv = -1;
    const int e = base + lane;
    if (e < NEDGE) {
        if (g_is64) {
            const long long* e64 = (const long long*)ei_raw;
            long long s = e64[e], d = e64[NEDGE + e];
            sv = (s >= 0 && s < N_NODES) ? (int)s : -1;
            dv = (d >= 0 && d < N_NODES) ? (int)d : -1;
        } else {
            const int* e32 = (const int*)ei_raw;
            int s = e32[e], d = e32[NEDGE + e];
            sv = (s >= 0 && s < N_NODES) ? s : -1;
            dv = (d >= 0 && d < N_NODES) ? d : -1;
        }
    }

#pragma unroll 8
    for (int j = 0; j < 32; j++) {
        int ss = __shfl_sync(0xffffffffu, sv, j);
        int dd = __shfl_sync(0xffffffffu, dv, j);
        if (ss < 0 || dd < 0) continue;
        float4 v = *reinterpret_cast<const float4*>(&x[(size_t)ss * HID + lane * 4]);
        float* p = &g_sum[(size_t)dd * HID + lane * 4];
        asm volatile("red.global.add.v4.f32 [%0], {%1, %2, %3, %4};"
                     :: "l"(p), "f"(v.x), "f"(v.y), "f"(v.z), "f"(v.w) : "memory");
    }
    // one count per edge (own lane's edge)
    if (sv >= 0 && dv >= 0) {
        float* c = &g_cnt[dv];
        asm volatile("red.global.add.f32 [%0], %1;" :: "l"(c), "f"(1.0f) : "memory");
    }
}

// ============================ fused MMA kernel (persistent) ============================
// A[m][k] row-major bf16 hi/lo, 128B rows, swizzle: off ^ ((off>>3)&0x70)
// B[k][n] row-major bf16 hi/lo, 256B rows, swizzle: off ^ ((off>>4)&0x70)

__device__ __forceinline__ void store_split4(char* hi_base, char* lo_base,
                                             uint32_t off, float4 v) {
    __nv_bfloat16 h0 = __float2bfloat16(v.x), h1 = __float2bfloat16(v.y);
    __nv_bfloat16 h2 = __float2bfloat16(v.z), h3 = __float2bfloat16(v.w);
    __nv_bfloat16 l0 = __float2bfloat16(v.x - __bfloat162float(h0));
    __nv_bfloat16 l1 = __float2bfloat16(v.y - __bfloat162float(h1));
    __nv_bfloat16 l2 = __float2bfloat16(v.z - __bfloat162float(h2));
    __nv_bfloat16 l3 = __float2bfloat16(v.w - __bfloat162float(h3));
    uint32_t sw = off ^ ((off >> 3) & 0x70);
    __nv_bfloat162 hp0, hp1, lp0, lp1;
    hp0.x = h0; hp0.y = h1; hp1.x = h2; hp1.y = h3;
    lp0.x = l0; lp0.y = l1; lp1.x = l2; lp1.y = l3;
    uint2 hw, lw;
    hw.x = *(uint32_t*)&hp0; hw.y = *(uint32_t*)&hp1;
    lw.x = *(uint32_t*)&lp0; lw.y = *(uint32_t*)&lp1;
    *(uint2*)(hi_base + sw) = hw;
    *(uint2*)(lo_base + sw) = lw;
}

__device__ __forceinline__ void fetch_a(float4* pf, int c, int row0,
                                        const float* __restrict__ x) {
    const int tid = threadIdx.x;
#pragma unroll
    for (int i = 0; i < 4; i++) {
        int idx = tid + i * 512;          // 128 rows x 16 k-quads
        int row = idx >> 4, q = idx & 15;
        int r = row0 + row;
        float4 v = make_float4(0.f, 0.f, 0.f, 0.f);
        if (r < N_NODES) {
            if (c < 2) {
                float sc = 1.0f / fmaxf(__ldg(&g_cnt[r]), 1.0f);
                float4 t = *(const float4*)&g_sum[(size_t)r * HID + c * 64 + q * 4];
                v.x = t.x * sc; v.y = t.y * sc; v.z = t.z * sc; v.w = t.w * sc;
            } else {
                v = *(const float4*)&x[(size_t)r * HID + (c - 2) * 64 + q * 4];
            }
        }
        pf[i] = v;
    }
}

__device__ __forceinline__ void store_a(char* smem, const float4* pf, int c) {
    const int tid = threadIdx.x;
    char* hi = smem + SM_A + (c & 1) * 32768;
    char* lo = hi + 16384;
#pragma unroll
    for (int i = 0; i < 4; i++) {
        int idx = tid + i * 512;
        int row = idx >> 4, q = idx & 15;
        store_split4(hi, lo, (uint32_t)(row * 128 + q * 8), pf[i]);
    }
}

__global__ void __launch_bounds__(512, 1)
k_fused(const float* __restrict__ x,
        const float* __restrict__ b_l,
        float* __restrict__ out) {
    extern __shared__ __align__(1024) char smem[];
    const uint32_t sbase = smem_u32(smem);
    const int tid  = threadIdx.x;
    const int wid  = tid >> 5;
    const int lane = tid & 31;
    const int wm = wid & 7;               // warp M coordinate (8): rows wm*16..+15
    const int wn = wid >> 3;              // warp N coordinate (2): cols wn*64..+63

    float* Wn = (float*)(smem + SM_WN);
    float* bs = (float*)(smem + SM_BS);
    float* Sp = (float*)(smem + SM_SP);
    float* Hp = (float*)(smem + SM_HP);

    // ---- one-time prologue: B image + tables ----
#pragma unroll
    for (int i = 0; i < 16; i++) {
        uint32_t off = (uint32_t)(tid + i * 512) * 16;
        cp_async16(sbase + SM_B + off, g_Bprep + off);
    }
    CP_COMMIT();
    if (tid < 128) bs[tid] = b_l[tid];
    for (int i = tid; i < HID * NCLS; i += 512) Wn[i] = g_Wn[i];
    CP_WAIT0();
    __syncthreads();

    const int lane15 = lane & 15, laneh = lane >> 4;
    const int bg = lane >> 3, brr = lane & 7;

    // ---- persistent tile loop ----
    for (int tile = blockIdx.x; tile < NTILES; tile += gridDim.x) {
        const int row0 = tile * TM;

        // stage chunk 0
        {
            float4 pf0[4];
            fetch_a(pf0, 0, row0, x);
            store_a(smem, pf0, 0);
        }
        __syncthreads();

        float acc[8][4];
#pragma unroll
        for (int j = 0; j < 8; j++)
#pragma unroll
            for (int p = 0; p < 4; p++) acc[j][p] = 0.f;

        float4 pf[4];
        for (int c = 0; c < 4; c++) {
            if (c < 3) fetch_a(pf, c + 1, row0, x);

            const uint32_t abase = sbase + SM_A + (c & 1) * 32768;
            const uint32_t bbase = sbase + SM_B;
#pragma unroll
            for (int ks = 0; ks < 4; ks++) {
                uint32_t ah[4], al[4];
                {
                    uint32_t off = (uint32_t)((wm * 16 + lane15) * 128
                                              + ks * 32 + laneh * 16);
                    uint32_t sw = off ^ ((off >> 3) & 0x70);
                    ldsm_x4(ah, abase + sw);
                    ldsm_x4(al, abase + 16384 + sw);
                }
                uint32_t bh[4][4], bl[4][4];
                int krow = c * 64 + ks * 16 + (bg & 1) * 8 + brr;
                int nof = (bg >> 1) * 16;
#pragma unroll
                for (int j2 = 0; j2 < 4; j2++) {
                    uint32_t off = (uint32_t)(krow * 256 + wn * 128 + j2 * 32 + nof);
                    uint32_t sw = off ^ ((off >> 4) & 0x70);
                    ldsm_x4_t(bh[j2], bbase + sw);
                    ldsm_x4_t(bl[j2], bbase + 65536 + sw);
                }
#pragma unroll
                for (int j = 0; j < 8; j++) {
                    const uint32_t* Bh = &bh[j >> 1][(j & 1) * 2];
                    const uint32_t* Bl = &bl[j >> 1][(j & 1) * 2];
                    mma_bf16(acc[j], ah, Bh[0], Bh[1]);
                    mma_bf16(acc[j], al, Bh[0], Bh[1]);
                    mma_bf16(acc[j], ah, Bl[0], Bl[1]);
                }
            }
            if (c < 3) {
                store_a(smem, pf, c + 1);
                __syncthreads();
            }
        }

        // epilogue: bias + row L2 partials + classifier partials
#pragma unroll
        for (int rr2 = 0; rr2 < 2; rr2++) {
            int row = wm * 16 + (lane >> 2) + rr2 * 8;
            float h[16];
            float ss = 0.f;
#pragma unroll
            for (int j = 0; j < 8; j++)
#pragma unroll
                for (int p = 0; p < 2; p++) {
                    int colloc = j * 8 + (lane & 3) * 2 + p;
                    float v = acc[j][rr2 * 2 + p] + bs[wn * 64 + colloc];
                    h[j * 2 + p] = v;
                    ss += v * v;
                }
            ss += __shfl_xor_sync(0xffffffffu, ss, 1);
            ss += __shfl_xor_sync(0xffffffffu, ss, 2);

            float pc[NCLS];
#pragma unroll
            for (int cc = 0; cc < NCLS; cc++) pc[cc] = 0.f;
#pragma unroll
            for (int jj = 0; jj < 16; jj++) {
                int col = wn * 64 + (jj >> 1) * 8 + (lane & 3) * 2 + (jj & 1);
                float v = h[jj];
                const float* wr = &Wn[col * NCLS];
#pragma unroll
                for (int cc = 0; cc < NCLS; cc++) pc[cc] += v * wr[cc];
            }
#pragma unroll
            for (int cc = 0; cc < NCLS; cc++) {
                pc[cc] += __shfl_xor_sync(0xffffffffu, pc[cc], 1);
                pc[cc] += __shfl_xor_sync(0xffffffffu, pc[cc], 2);
            }
            if ((lane & 3) == 0) {
                Sp[wn * 128 + row] = ss;
                float* hp = &Hp[(wn * 128 + row) * NCLS];
#pragma unroll
                for (int cc = 0; cc < NCLS; cc++) hp[cc] = pc[cc];
            }
        }
        __syncthreads();

        // combine halves + write
        for (int i = tid; i < TM * NCLS; i += 512) {
            int r = i / NCLS, cc = i % NCLS;
            int gr = row0 + r;
            if (gr >= N_NODES) continue;
            float ssum = Sp[r] + Sp[128 + r];
            float rinv = 1.0f / fmaxf(sqrtf(ssum), 1e-12f);
            out[(size_t)gr * NCLS + cc] = (Hp[r * NCLS + cc] + Hp[(128 + r) * NCLS + cc]) * rinv;
        }
        // next tile's A store is safe: all compute synced above; Sp/Hp rewrites
        // are gated by the next tile's mainloop syncs.
    }
}

// ---------------------------------------------------------------------------
extern "C" void kernel_launch(void* const* d_in, const int* in_sizes, int n_in,
                              void* d_out, int out_size) {
    const float* x     = (const float*)d_in[0];
    const void*  ei    = d_in[1];
    const float* W_l   = (const float*)d_in[2];
    const float* b_l   = (const float*)d_in[3];
    const float* W_r   = (const float*)d_in[4];
    const float* W_cls = (const float*)d_in[5];
    float*       out   = (float*)d_out;

    cudaFuncSetAttribute(k_fused, cudaFuncAttributeMaxDynamicSharedMemorySize, SM_TOTAL);

    k_init<<<17 + 1024, 512>>>(ei, W_l, W_r, W_cls);

    int nwarps = (NEDGE + 31) / 32;
    int sthreads = nwarps * 32;
    k_scatter<<<(sthreads + 255) / 256, 256>>>(x, ei);

    k_fused<<<GRID_F, 512, SM_TOTAL>>>(x, b_l, out);
}